// round 1
// baseline (speedup 1.0000x reference)
#include <cuda_runtime.h>
#include <math.h>

// Problem constants
#define NT   4096   // B*T tokens
#define DD   1024   // model dim
#define HH   4096   // hidden dim
#define NE   8      // experts
#define TOPK 2

// ---------------- scratch (static __device__, no allocation) ----------------
__device__ int   g_cnt[NE];              // tokens routed to each expert
__device__ int   g_tok [NE * NT];        // token id per (expert, slot)
__device__ float g_gw  [NE * NT];        // gate weight per (expert, slot)
__device__ int   g_hrow[NE * NT];        // h-buffer row (= token*2 + k) per slot
__device__ float g_h[(size_t)NT * TOPK * HH];   // 8192 x 4096 fp32 = 134 MB

// ---------------- kernel 0: zero output + counters ----------------
__global__ void k_zero(float* __restrict__ out) {
    int i = blockIdx.x * blockDim.x + threadIdx.x;
    if (i < NT * DD) out[i] = 0.0f;
    if (i < NE) g_cnt[i] = 0;
}

// ---------------- kernel 1: gating (softmax + top-2 + compaction) ----------------
// one warp per token
__global__ void k_gate(const float* __restrict__ x,
                       const float* __restrict__ gw,
                       const float* __restrict__ gb) {
    int warp = (blockIdx.x * blockDim.x + threadIdx.x) >> 5;
    int lane = threadIdx.x & 31;
    if (warp >= NT) return;

    const float* xr = x + (size_t)warp * DD;
    float acc[NE];
#pragma unroll
    for (int e = 0; e < NE; e++) acc[e] = 0.0f;

    for (int d = lane; d < DD; d += 32) {
        float xv = xr[d];
#pragma unroll
        for (int e = 0; e < NE; e++) acc[e] += xv * gw[d * NE + e];
    }
#pragma unroll
    for (int e = 0; e < NE; e++) {
#pragma unroll
        for (int o = 16; o > 0; o >>= 1)
            acc[e] += __shfl_xor_sync(0xffffffffu, acc[e], o);
    }

    if (lane == 0) {
        float z[NE];
        float m = -1e30f;
#pragma unroll
        for (int e = 0; e < NE; e++) { z[e] = acc[e] + gb[e]; m = fmaxf(m, z[e]); }
        float s = 0.0f;
#pragma unroll
        for (int e = 0; e < NE; e++) { z[e] = expf(z[e] - m); s += z[e]; }
        // top-2, first index wins ties (matches jax.lax.top_k)
        int i1 = 0;
#pragma unroll
        for (int e = 1; e < NE; e++) if (z[e] > z[i1]) i1 = e;
        int i2 = (i1 == 0) ? 1 : 0;
#pragma unroll
        for (int e = 0; e < NE; e++) if (e != i1 && z[e] > z[i2]) i2 = e;

        float inv = 1.0f / s;
        int es[2] = { i1, i2 };
#pragma unroll
        for (int k = 0; k < TOPK; k++) {
            int e = es[k];
            int slot = atomicAdd(&g_cnt[e], 1);
            g_tok [e * NT + slot] = warp;
            g_gw  [e * NT + slot] = z[e] * inv;
            g_hrow[e * NT + slot] = warp * TOPK + k;
        }
    }
}

// ---------------- grouped GEMM tiles ----------------
#define BM 64
#define BN 64
#define BK 16

// FC1: h[hrow] = relu( x[tok] @ w1[e] + b1[e] )   per expert group
__global__ void k_fc1(const float* __restrict__ x,
                      const float* __restrict__ w1,
                      const float* __restrict__ b1) {
    int e   = blockIdx.z;
    int cnt = g_cnt[e];
    int m0  = blockIdx.y * BM;
    if (m0 >= cnt) return;
    int n0  = blockIdx.x * BN;

    __shared__ float As[BK][BM + 1];
    __shared__ float Bs[BK][BN];
    __shared__ int   toks[BM];
    __shared__ int   hrows[BM];

    int tid = threadIdx.x;           // 256 threads
    int tx  = tid & 15;              // 16 x 16 thread grid
    int ty  = tid >> 4;

    if (tid < BM) {
        int s = m0 + tid;
        toks [tid] = (s < cnt) ? g_tok [e * NT + s] : -1;
        hrows[tid] = (s < cnt) ? g_hrow[e * NT + s] : -1;
    }
    __syncthreads();

    const float* wB = w1 + (size_t)e * DD * HH;

    float acc[4][4];
#pragma unroll
    for (int i = 0; i < 4; i++)
#pragma unroll
        for (int j = 0; j < 4; j++) acc[i][j] = 0.0f;

    for (int k0 = 0; k0 < DD; k0 += BK) {
        // A tile: 64 rows x 16 k, one float4 per thread (gathered rows)
        {
            int s   = tid >> 2;            // 0..63
            int kk4 = (tid & 3) * 4;       // 0,4,8,12
            int t   = toks[s];
            float4 v = make_float4(0.f, 0.f, 0.f, 0.f);
            if (t >= 0)
                v = *(const float4*)&x[(size_t)t * DD + k0 + kk4];
            As[kk4 + 0][s] = v.x;
            As[kk4 + 1][s] = v.y;
            As[kk4 + 2][s] = v.z;
            As[kk4 + 3][s] = v.w;
        }
        // B tile: 16 k x 64 n, one float4 per thread (coalesced)
        {
            int kk = tid >> 4;             // 0..15
            int n4 = (tid & 15) * 4;       // 0..60
            float4 v = *(const float4*)&wB[(size_t)(k0 + kk) * HH + n0 + n4];
            *(float4*)&Bs[kk][n4] = v;
        }
        __syncthreads();
#pragma unroll
        for (int kk = 0; kk < BK; kk++) {
            float a0 = As[kk][ty * 4 + 0];
            float a1 = As[kk][ty * 4 + 1];
            float a2 = As[kk][ty * 4 + 2];
            float a3 = As[kk][ty * 4 + 3];
            float4 bv = *(float4*)&Bs[kk][tx * 4];
            acc[0][0] += a0 * bv.x; acc[0][1] += a0 * bv.y; acc[0][2] += a0 * bv.z; acc[0][3] += a0 * bv.w;
            acc[1][0] += a1 * bv.x; acc[1][1] += a1 * bv.y; acc[1][2] += a1 * bv.z; acc[1][3] += a1 * bv.w;
            acc[2][0] += a2 * bv.x; acc[2][1] += a2 * bv.y; acc[2][2] += a2 * bv.z; acc[2][3] += a2 * bv.w;
            acc[3][0] += a3 * bv.x; acc[3][1] += a3 * bv.y; acc[3][2] += a3 * bv.z; acc[3][3] += a3 * bv.w;
        }
        __syncthreads();
    }

#pragma unroll
    for (int i = 0; i < 4; i++) {
        int s  = ty * 4 + i;
        int hr = hrows[s];
        if (hr < 0) continue;
        float* hout = &g_h[(size_t)hr * HH + n0 + tx * 4];
        const float* bb = &b1[e * HH + n0 + tx * 4];
#pragma unroll
        for (int j = 0; j < 4; j++)
            hout[j] = fmaxf(acc[i][j] + bb[j], 0.0f);
    }
}

// FC2: out[tok] += gate * ( h[hrow] @ w2[e] + b2[e] )   per expert group
__global__ void k_fc2(const float* __restrict__ w2,
                      const float* __restrict__ b2,
                      float* __restrict__ out) {
    int e   = blockIdx.z;
    int cnt = g_cnt[e];
    int m0  = blockIdx.y * BM;
    if (m0 >= cnt) return;
    int n0  = blockIdx.x * BN;

    __shared__ float As[BK][BM + 1];
    __shared__ float Bs[BK][BN];
    __shared__ int   toks[BM];
    __shared__ int   hrows[BM];
    __shared__ float gws[BM];

    int tid = threadIdx.x;
    int tx  = tid & 15;
    int ty  = tid >> 4;

    if (tid < BM) {
        int s = m0 + tid;
        toks [tid] = (s < cnt) ? g_tok [e * NT + s] : -1;
        hrows[tid] = (s < cnt) ? g_hrow[e * NT + s] : -1;
        gws  [tid] = (s < cnt) ? g_gw  [e * NT + s] : 0.0f;
    }
    __syncthreads();

    const float* wB = w2 + (size_t)e * HH * DD;

    float acc[4][4];
#pragma unroll
    for (int i = 0; i < 4; i++)
#pragma unroll
        for (int j = 0; j < 4; j++) acc[i][j] = 0.0f;

    for (int k0 = 0; k0 < HH; k0 += BK) {
        {
            int s   = tid >> 2;
            int kk4 = (tid & 3) * 4;
            int hr  = hrows[s];
            float4 v = make_float4(0.f, 0.f, 0.f, 0.f);
            if (hr >= 0)
                v = *(const float4*)&g_h[(size_t)hr * HH + k0 + kk4];
            As[kk4 + 0][s] = v.x;
            As[kk4 + 1][s] = v.y;
            As[kk4 + 2][s] = v.z;
            As[kk4 + 3][s] = v.w;
        }
        {
            int kk = tid >> 4;
            int n4 = (tid & 15) * 4;
            float4 v = *(const float4*)&wB[(size_t)(k0 + kk) * DD + n0 + n4];
            *(float4*)&Bs[kk][n4] = v;
        }
        __syncthreads();
#pragma unroll
        for (int kk = 0; kk < BK; kk++) {
            float a0 = As[kk][ty * 4 + 0];
            float a1 = As[kk][ty * 4 + 1];
            float a2 = As[kk][ty * 4 + 2];
            float a3 = As[kk][ty * 4 + 3];
            float4 bv = *(float4*)&Bs[kk][tx * 4];
            acc[0][0] += a0 * bv.x; acc[0][1] += a0 * bv.y; acc[0][2] += a0 * bv.z; acc[0][3] += a0 * bv.w;
            acc[1][0] += a1 * bv.x; acc[1][1] += a1 * bv.y; acc[1][2] += a1 * bv.z; acc[1][3] += a1 * bv.w;
            acc[2][0] += a2 * bv.x; acc[2][1] += a2 * bv.y; acc[2][2] += a2 * bv.z; acc[2][3] += a2 * bv.w;
            acc[3][0] += a3 * bv.x; acc[3][1] += a3 * bv.y; acc[3][2] += a3 * bv.z; acc[3][3] += a3 * bv.w;
        }
        __syncthreads();
    }

#pragma unroll
    for (int i = 0; i < 4; i++) {
        int s = ty * 4 + i;
        int t = toks[s];
        if (t < 0) continue;
        float g = gws[s];
        float* orow = &out[(size_t)t * DD + n0 + tx * 4];
        const float* bb = &b2[e * DD + n0 + tx * 4];
#pragma unroll
        for (int j = 0; j < 4; j++)
            atomicAdd(&orow[j], g * (acc[i][j] + bb[j]));
    }
}

// ---------------- launch ----------------
extern "C" void kernel_launch(void* const* d_in, const int* in_sizes, int n_in,
                              void* d_out, int out_size) {
    const float* x  = (const float*)d_in[0];
    const float* gw = (const float*)d_in[1];
    const float* gb = (const float*)d_in[2];
    const float* w1 = (const float*)d_in[3];
    const float* b1 = (const float*)d_in[4];
    const float* w2 = (const float*)d_in[5];
    const float* b2 = (const float*)d_in[6];
    float* out = (float*)d_out;

    k_zero<<<(NT * DD + 255) / 256, 256>>>(out);
    k_gate<<<NT / 4, 128>>>(x, gw, gb);

    dim3 g1(HH / BN, NT / BM, NE);   // 64 x 64 x 8 (blocks beyond group count exit)
    k_fc1<<<g1, 256>>>(x, w1, b1);

    dim3 g2(DD / BN, NT / BM, NE);   // 16 x 64 x 8
    k_fc2<<<g2, 256>>>(w2, b2, out);
}

// round 6
// speedup vs baseline: 3.2456x; 3.2456x over previous
#include <cuda_runtime.h>
#include <cuda_bf16.h>
#include <math.h>
#include <stdint.h>

// Problem constants
#define NT   4096   // B*T tokens
#define DD   1024   // model dim
#define HH   4096   // hidden dim
#define NE   8      // experts
#define TOPK 2

#define BM 128
#define BN 64
#define KC 32

// ---------------- scratch (static device, no allocation) ----------------
__device__ int   g_cnt[NE];
__device__ int   g_tok [NE * NT];
__device__ float g_gw  [NE * NT];
__device__ int   g_hrow[NE * NT];

__device__ __nv_bfloat16 g_xh[(size_t)NT * DD];
__device__ __nv_bfloat16 g_xl[(size_t)NT * DD];
__device__ __nv_bfloat16 g_w1h[(size_t)NE * DD * HH];
__device__ __nv_bfloat16 g_w1l[(size_t)NE * DD * HH];
__device__ __nv_bfloat16 g_w2h[(size_t)NE * HH * DD];
__device__ __nv_bfloat16 g_w2l[(size_t)NE * HH * DD];
__device__ __nv_bfloat16 g_hh[(size_t)NT * TOPK * HH];
__device__ __nv_bfloat16 g_hl[(size_t)NT * TOPK * HH];
__device__ float g_y[(size_t)NT * TOPK * DD];

// ---------------- PTX helpers (plain sm_103-safe: no tcgen05/TMA) ----------------
__device__ __forceinline__ uint32_t smem_u32(const void* p) {
    uint32_t a;
    asm("{ .reg .u64 t; cvta.to.shared.u64 t, %1; cvt.u32.u64 %0, t; }" : "=r"(a) : "l"(p));
    return a;
}
__device__ __forceinline__ void cp16(uint32_t dst, const void* src, uint32_t srcsize) {
    asm volatile("cp.async.cg.shared.global [%0], [%1], 16, %2;"
                 :: "r"(dst), "l"(src), "r"(srcsize) : "memory");
}
#define CP_COMMIT()  asm volatile("cp.async.commit_group;" ::: "memory")
#define CP_WAIT1()   asm volatile("cp.async.wait_group 1;" ::: "memory")
#define CP_WAIT0()   asm volatile("cp.async.wait_group 0;" ::: "memory")

__device__ __forceinline__ void ldsm4(uint32_t* r, uint32_t addr) {
    asm volatile("ldmatrix.sync.aligned.m8n8.x4.shared.b16 {%0,%1,%2,%3}, [%4];"
                 : "=r"(r[0]), "=r"(r[1]), "=r"(r[2]), "=r"(r[3]) : "r"(addr));
}
__device__ __forceinline__ void ldsm4t(uint32_t* r, uint32_t addr) {
    asm volatile("ldmatrix.sync.aligned.m8n8.x4.trans.shared.b16 {%0,%1,%2,%3}, [%4];"
                 : "=r"(r[0]), "=r"(r[1]), "=r"(r[2]), "=r"(r[3]) : "r"(addr));
}
__device__ __forceinline__ void mma16816(float* d, const uint32_t* a, uint32_t b0, uint32_t b1) {
    asm volatile("mma.sync.aligned.m16n8k16.row.col.f32.bf16.bf16.f32 "
                 "{%0,%1,%2,%3}, {%4,%5,%6,%7}, {%8,%9}, {%0,%1,%2,%3};"
                 : "+f"(d[0]), "+f"(d[1]), "+f"(d[2]), "+f"(d[3])
                 : "r"(a[0]), "r"(a[1]), "r"(a[2]), "r"(a[3]), "r"(b0), "r"(b1));
}

// ---------------- SMEM layout ----------------
#define AST 80     // A row stride bytes (64B data + 16 pad) -> conflict-free ldmatrix
#define BST 144    // B row stride bytes (128B data + 16 pad)
#define OFF_TOK  0
#define OFF_HR   512
#define OFF_GWS  1024
#define OFF_TILE 1536
#define A_HI 0
#define A_LO 10240
#define B_HI 20480
#define B_LO 25088
#define BUF_SZ 29696
#define SMEM_SZ (OFF_TILE + 2 * BUF_SZ)   // 60928

// ---------------- kernel 0: zero counters ----------------
__global__ void k_zero() { if (threadIdx.x < NE) g_cnt[threadIdx.x] = 0; }

// ---------------- gating: one warp per token ----------------
__global__ void k_gate(const float* __restrict__ x,
                       const float* __restrict__ gw,
                       const float* __restrict__ gb) {
    int warp = (blockIdx.x * blockDim.x + threadIdx.x) >> 5;
    int lane = threadIdx.x & 31;
    if (warp >= NT) return;
    const float* xr = x + (size_t)warp * DD;
    float acc[NE];
#pragma unroll
    for (int e = 0; e < NE; e++) acc[e] = 0.0f;
    for (int d = lane; d < DD; d += 32) {
        float xv = xr[d];
#pragma unroll
        for (int e = 0; e < NE; e++) acc[e] += xv * gw[d * NE + e];
    }
#pragma unroll
    for (int e = 0; e < NE; e++) {
#pragma unroll
        for (int o = 16; o > 0; o >>= 1)
            acc[e] += __shfl_xor_sync(0xffffffffu, acc[e], o);
    }
    if (lane == 0) {
        float z[NE]; float m = -1e30f;
#pragma unroll
        for (int e = 0; e < NE; e++) { z[e] = acc[e] + gb[e]; m = fmaxf(m, z[e]); }
        float s = 0.0f;
#pragma unroll
        for (int e = 0; e < NE; e++) { z[e] = expf(z[e] - m); s += z[e]; }
        int i1 = 0;
#pragma unroll
        for (int e = 1; e < NE; e++) if (z[e] > z[i1]) i1 = e;
        int i2 = (i1 == 0) ? 1 : 0;
#pragma unroll
        for (int e = 0; e < NE; e++) if (e != i1 && z[e] > z[i2]) i2 = e;
        float inv = 1.0f / s;
        int es[2] = { i1, i2 };
#pragma unroll
        for (int k = 0; k < TOPK; k++) {
            int e = es[k];
            int slot = atomicAdd(&g_cnt[e], 1);
            g_tok [e * NT + slot] = warp;
            g_gw  [e * NT + slot] = z[e] * inv;
            g_hrow[e * NT + slot] = warp * TOPK + k;
        }
    }
}

// ---------------- fp32 -> bf16 hi/lo preconvert ----------------
__global__ void k_conv(const float* __restrict__ src,
                       __nv_bfloat16* __restrict__ hi,
                       __nv_bfloat16* __restrict__ lo, int n4) {
    int i = blockIdx.x * blockDim.x + threadIdx.x;
    if (i >= n4) return;
    float4 v = ((const float4*)src)[i];
    float f[4] = { v.x, v.y, v.z, v.w };
    unsigned short h[4], l[4];
#pragma unroll
    for (int j = 0; j < 4; j++) {
        __nv_bfloat16 hb = __float2bfloat16(f[j]);
        float r = f[j] - __bfloat162float(hb);
        __nv_bfloat16 lb = __float2bfloat16(r);
        h[j] = *(unsigned short*)&hb;
        l[j] = *(unsigned short*)&lb;
    }
    uint2 hp, lp;
    hp.x = ((uint32_t)h[1] << 16) | h[0]; hp.y = ((uint32_t)h[3] << 16) | h[2];
    lp.x = ((uint32_t)l[1] << 16) | l[0]; lp.y = ((uint32_t)l[3] << 16) | l[2];
    ((uint2*)hi)[i] = hp;
    ((uint2*)lo)[i] = lp;
}

// ---------------- tile fill (cp.async) ----------------
__device__ __forceinline__ void fill_tiles(uint32_t tb, int tid,
                                           const __nv_bfloat16* __restrict__ ah,
                                           const __nv_bfloat16* __restrict__ al,
                                           int a_ld, const int* rows,
                                           const __nv_bfloat16* __restrict__ bh,
                                           const __nv_bfloat16* __restrict__ bl,
                                           int b_ld, int n0, int k0) {
    // A: 128 rows x 32 bf16 (4 x 16B chunks/row), hi + lo
#pragma unroll
    for (int i = 0; i < 2; i++) {
        int id = tid + i * 256;
        int r = id >> 2, c = id & 3;
        int t = rows[r];
        size_t off = (size_t)(t < 0 ? 0 : t) * a_ld + k0 + c * 8;
        uint32_t sz = (t < 0) ? 0u : 16u;
        cp16(tb + A_HI + r * AST + c * 16, ah + off, sz);
        cp16(tb + A_LO + r * AST + c * 16, al + off, sz);
    }
    // B: 32 rows (k) x 64 bf16 (8 x 16B chunks/row), hi + lo
    {
        int r = tid >> 3, c = tid & 7;
        size_t off = (size_t)(k0 + r) * b_ld + n0 + c * 8;
        cp16(tb + B_HI + r * BST + c * 16, bh + off, 16);
        cp16(tb + B_LO + r * BST + c * 16, bl + off, 16);
    }
}

// ---------------- mma mainloop for one chunk ----------------
__device__ __forceinline__ void compute_chunk(uint32_t tb, int lane, int wm, int wn,
                                              float acc[2][4][4]) {
    int t  = lane >> 3;
    int lr = lane & 7;
#pragma unroll
    for (int k16 = 0; k16 < KC; k16 += 16) {
        uint32_t ah[2][4], al_[2][4];
#pragma unroll
        for (int mt = 0; mt < 2; mt++) {
            uint32_t addr = tb + A_HI + (uint32_t)(wm + mt * 16 + (t & 1) * 8 + lr) * AST
                          + (uint32_t)(k16 + (t >> 1) * 8) * 2;
            ldsm4(ah[mt], addr);
        }
        // split 1: Ah * Bh
#pragma unroll
        for (int j = 0; j < 2; j++) {
            uint32_t b[4];
            uint32_t addr = tb + B_HI + (uint32_t)(k16 + (t & 1) * 8 + lr) * BST
                          + (uint32_t)(wn + j * 16 + (t >> 1) * 8) * 2;
            ldsm4t(b, addr);
#pragma unroll
            for (int mt = 0; mt < 2; mt++) {
                mma16816(acc[mt][j * 2 + 0], ah[mt], b[0], b[1]);
                mma16816(acc[mt][j * 2 + 1], ah[mt], b[2], b[3]);
            }
        }
        // split 2: Ah * Bl
#pragma unroll
        for (int j = 0; j < 2; j++) {
            uint32_t b[4];
            uint32_t addr = tb + B_LO + (uint32_t)(k16 + (t & 1) * 8 + lr) * BST
                          + (uint32_t)(wn + j * 16 + (t >> 1) * 8) * 2;
            ldsm4t(b, addr);
#pragma unroll
            for (int mt = 0; mt < 2; mt++) {
                mma16816(acc[mt][j * 2 + 0], ah[mt], b[0], b[1]);
                mma16816(acc[mt][j * 2 + 1], ah[mt], b[2], b[3]);
            }
        }
        // split 3: Al * Bh
#pragma unroll
        for (int mt = 0; mt < 2; mt++) {
            uint32_t addr = tb + A_LO + (uint32_t)(wm + mt * 16 + (t & 1) * 8 + lr) * AST
                          + (uint32_t)(k16 + (t >> 1) * 8) * 2;
            ldsm4(al_[mt], addr);
        }
#pragma unroll
        for (int j = 0; j < 2; j++) {
            uint32_t b[4];
            uint32_t addr = tb + B_HI + (uint32_t)(k16 + (t & 1) * 8 + lr) * BST
                          + (uint32_t)(wn + j * 16 + (t >> 1) * 8) * 2;
            ldsm4t(b, addr);
#pragma unroll
            for (int mt = 0; mt < 2; mt++) {
                mma16816(acc[mt][j * 2 + 0], al_[mt], b[0], b[1]);
                mma16816(acc[mt][j * 2 + 1], al_[mt], b[2], b[3]);
            }
        }
    }
}

// ---------------- FC1: h[hrow] = relu(x[tok] @ w1[e] + b1[e]) -> bf16 hi/lo ----------------
__global__ void __launch_bounds__(256, 2)
k_fc1(const float* __restrict__ b1) {
    int e = blockIdx.z;
    int cnt = g_cnt[e];
    int m0 = blockIdx.y * BM;
    if (m0 >= cnt) return;
    int n0 = blockIdx.x * BN;

    extern __shared__ char smem[];
    uint32_t sb = smem_u32(smem);
    int tid = threadIdx.x, wid = tid >> 5, lane = tid & 31;
    int* toks  = (int*)(smem + OFF_TOK);
    int* hrows = (int*)(smem + OFF_HR);
    if (tid < BM) {
        int s = m0 + tid;
        toks [tid] = (s < cnt) ? g_tok [e * NT + s] : -1;
        hrows[tid] = (s < cnt) ? g_hrow[e * NT + s] : -1;
    }
    __syncthreads();

    const __nv_bfloat16* wh = g_w1h + (size_t)e * DD * HH;
    const __nv_bfloat16* wl = g_w1l + (size_t)e * DD * HH;

    float acc[2][4][4];
#pragma unroll
    for (int a = 0; a < 2; a++)
#pragma unroll
        for (int b = 0; b < 4; b++)
#pragma unroll
            for (int c = 0; c < 4; c++) acc[a][b][c] = 0.0f;

    int wm = (wid >> 1) * 32, wn = (wid & 1) * 32;
    const int NCH = DD / KC;   // 32

    fill_tiles(sb + OFF_TILE, tid, g_xh, g_xl, DD, toks, wh, wl, HH, n0, 0);
    CP_COMMIT();
    int buf = 0;
    for (int c = 0; c < NCH; c++) {
        if (c + 1 < NCH) {
            fill_tiles(sb + OFF_TILE + (buf ^ 1) * BUF_SZ, tid, g_xh, g_xl, DD, toks,
                       wh, wl, HH, n0, (c + 1) * KC);
            CP_COMMIT();
            CP_WAIT1();
        } else {
            CP_WAIT0();
        }
        __syncthreads();
        compute_chunk(sb + OFF_TILE + buf * BUF_SZ, lane, wm, wn, acc);
        __syncthreads();
        buf ^= 1;
    }

    // epilogue: relu + bias, split to bf16 hi/lo
    const float* bb = b1 + (size_t)e * HH + n0;
#pragma unroll
    for (int mt = 0; mt < 2; mt++) {
#pragma unroll
        for (int nt = 0; nt < 4; nt++) {
            int col = wn + nt * 8 + (lane & 3) * 2;
            float bv0 = bb[col], bv1 = bb[col + 1];
#pragma unroll
            for (int half = 0; half < 2; half++) {
                int li = wm + mt * 16 + (lane >> 2) + half * 8;
                int hr = hrows[li];
                if (hr < 0) continue;
                float h0 = fmaxf(acc[mt][nt][half * 2 + 0] + bv0, 0.0f);
                float h1 = fmaxf(acc[mt][nt][half * 2 + 1] + bv1, 0.0f);
                __nv_bfloat16 hh0 = __float2bfloat16(h0);
                __nv_bfloat16 hh1 = __float2bfloat16(h1);
                __nv_bfloat16 hl0 = __float2bfloat16(h0 - __bfloat162float(hh0));
                __nv_bfloat16 hl1 = __float2bfloat16(h1 - __bfloat162float(hh1));
                size_t off = (size_t)hr * HH + n0 + col;
                uint32_t hp = ((uint32_t)(*(unsigned short*)&hh1) << 16) | (*(unsigned short*)&hh0);
                uint32_t lp = ((uint32_t)(*(unsigned short*)&hl1) << 16) | (*(unsigned short*)&hl0);
                *(uint32_t*)(g_hh + off) = hp;
                *(uint32_t*)(g_hl + off) = lp;
            }
        }
    }
}

// ---------------- FC2: y[hrow] = gate * (h[hrow] @ w2[e] + b2[e]) ----------------
__global__ void __launch_bounds__(256, 2)
k_fc2(const float* __restrict__ b2) {
    int e = blockIdx.z;
    int cnt = g_cnt[e];
    int m0 = blockIdx.y * BM;
    if (m0 >= cnt) return;
    int n0 = blockIdx.x * BN;

    extern __shared__ char smem[];
    uint32_t sb = smem_u32(smem);
    int tid = threadIdx.x, wid = tid >> 5, lane = tid & 31;
    int*   hrows = (int*)(smem + OFF_HR);
    float* gws   = (float*)(smem + OFF_GWS);
    if (tid < BM) {
        int s = m0 + tid;
        hrows[tid] = (s < cnt) ? g_hrow[e * NT + s] : -1;
        gws  [tid] = (s < cnt) ? g_gw  [e * NT + s] : 0.0f;
    }
    __syncthreads();

    const __nv_bfloat16* wh = g_w2h + (size_t)e * HH * DD;
    const __nv_bfloat16* wl = g_w2l + (size_t)e * HH * DD;

    float acc[2][4][4];
#pragma unroll
    for (int a = 0; a < 2; a++)
#pragma unroll
        for (int b = 0; b < 4; b++)
#pragma unroll
            for (int c = 0; c < 4; c++) acc[a][b][c] = 0.0f;

    int wm = (wid >> 1) * 32, wn = (wid & 1) * 32;
    const int NCH = HH / KC;   // 128

    fill_tiles(sb + OFF_TILE, tid, g_hh, g_hl, HH, hrows, wh, wl, DD, n0, 0);
    CP_COMMIT();
    int buf = 0;
    for (int c = 0; c < NCH; c++) {
        if (c + 1 < NCH) {
            fill_tiles(sb + OFF_TILE + (buf ^ 1) * BUF_SZ, tid, g_hh, g_hl, HH, hrows,
                       wh, wl, DD, n0, (c + 1) * KC);
            CP_COMMIT();
            CP_WAIT1();
        } else {
            CP_WAIT0();
        }
        __syncthreads();
        compute_chunk(sb + OFF_TILE + buf * BUF_SZ, lane, wm, wn, acc);
        __syncthreads();
        buf ^= 1;
    }

    const float* bb = b2 + (size_t)e * DD + n0;
#pragma unroll
    for (int mt = 0; mt < 2; mt++) {
#pragma unroll
        for (int nt = 0; nt < 4; nt++) {
            int col = wn + nt * 8 + (lane & 3) * 2;
            float bv0 = bb[col], bv1 = bb[col + 1];
#pragma unroll
            for (int half = 0; half < 2; half++) {
                int li = wm + mt * 16 + (lane >> 2) + half * 8;
                int hr = hrows[li];
                if (hr < 0) continue;
                float g = gws[li];
                float2 o;
                o.x = g * (acc[mt][nt][half * 2 + 0] + bv0);
                o.y = g * (acc[mt][nt][half * 2 + 1] + bv1);
                *(float2*)(g_y + (size_t)hr * DD + n0 + col) = o;
            }
        }
    }
}

// ---------------- combine: out[t] = y[2t] + y[2t+1] ----------------
__global__ void k_combine(float* __restrict__ out) {
    int i = blockIdx.x * blockDim.x + threadIdx.x;
    if (i >= NT * DD / 4) return;
    int t  = i >> 8;
    int d4 = i & 255;
    const float4* y4 = (const float4*)g_y;
    float4 a = y4[(size_t)(2 * t) * 256 + d4];
    float4 b = y4[(size_t)(2 * t + 1) * 256 + d4];
    float4 o; o.x = a.x + b.x; o.y = a.y + b.y; o.z = a.z + b.z; o.w = a.w + b.w;
    ((float4*)out)[i] = o;
}

// ---------------- launch ----------------
extern "C" void kernel_launch(void* const* d_in, const int* in_sizes, int n_in,
                              void* d_out, int out_size) {
    const float* x  = (const float*)d_in[0];
    const float* gw = (const float*)d_in[1];
    const float* gb = (const float*)d_in[2];
    const float* w1 = (const float*)d_in[3];
    const float* b1 = (const float*)d_in[4];
    const float* w2 = (const float*)d_in[5];
    const float* b2 = (const float*)d_in[6];
    float* out = (float*)d_out;

    cudaFuncSetAttribute(k_fc1, cudaFuncAttributeMaxDynamicSharedMemorySize, SMEM_SZ);
    cudaFuncSetAttribute(k_fc2, cudaFuncAttributeMaxDynamicSharedMemorySize, SMEM_SZ);

    k_zero<<<1, 32>>>();
    k_gate<<<NT / 4, 128>>>(x, gw, gb);

    // preconvert fp32 -> bf16 hi/lo
    __nv_bfloat16 *xh, *xl, *w1h, *w1l, *w2h, *w2l;
    cudaGetSymbolAddress((void**)&xh,  g_xh);
    cudaGetSymbolAddress((void**)&xl,  g_xl);
    cudaGetSymbolAddress((void**)&w1h, g_w1h);
    cudaGetSymbolAddress((void**)&w1l, g_w1l);
    cudaGetSymbolAddress((void**)&w2h, g_w2h);
    cudaGetSymbolAddress((void**)&w2l, g_w2l);

    int nx = NT * DD / 4;                 // 1,048,576
    int nw = NE * DD * HH / 4;            // 8,388,608
    k_conv<<<(nx + 255) / 256, 256>>>(x,  xh,  xl,  nx);
    k_conv<<<(nw + 255) / 256, 256>>>(w1, w1h, w1l, nw);
    k_conv<<<(nw + 255) / 256, 256>>>(w2, w2h, w2l, nw);

    dim3 g1(HH / BN, NT / BM, NE);   // 64 x 32 x 8
    k_fc1<<<g1, 256, SMEM_SZ>>>(b1);

    dim3 g2(DD / BN, NT / BM, NE);   // 16 x 32 x 8
    k_fc2<<<g2, 256, SMEM_SZ>>>(b2);

    k_combine<<<(NT * DD / 4 + 255) / 256, 256>>>(out);
}

// round 7
// speedup vs baseline: 7.5982x; 2.3411x over previous
#include <cuda_runtime.h>
#include <cuda_fp16.h>
#include <math.h>
#include <stdint.h>

// Problem constants
#define NT   4096   // B*T tokens
#define DD   1024   // model dim
#define HH   4096   // hidden dim
#define NE   8      // experts
#define TOPK 2

#define BM 128
#define BN 128
#define KC 32

// ---------------- scratch (static device, no allocation) ----------------
__device__ int   g_cnt[NE];
__device__ int   g_tok [NE * NT];
__device__ float g_gw  [NE * NT];
__device__ int   g_hrow[NE * NT];

__device__ __half g_xf[(size_t)NT * DD];
__device__ __half g_w1f[(size_t)NE * DD * HH];
__device__ __half g_w2f[(size_t)NE * HH * DD];
__device__ __half g_hf[(size_t)NT * TOPK * HH];
__device__ float  g_y[(size_t)NT * TOPK * DD];

// ---------------- PTX helpers (plain sm_103-safe) ----------------
__device__ __forceinline__ uint32_t smem_u32(const void* p) {
    uint32_t a;
    asm("{ .reg .u64 t; cvta.to.shared.u64 t, %1; cvt.u32.u64 %0, t; }" : "=r"(a) : "l"(p));
    return a;
}
__device__ __forceinline__ void cp16(uint32_t dst, const void* src, uint32_t srcsize) {
    asm volatile("cp.async.cg.shared.global [%0], [%1], 16, %2;"
                 :: "r"(dst), "l"(src), "r"(srcsize) : "memory");
}
#define CP_COMMIT()  asm volatile("cp.async.commit_group;" ::: "memory")
#define CP_WAIT1()   asm volatile("cp.async.wait_group 1;" ::: "memory")
#define CP_WAIT0()   asm volatile("cp.async.wait_group 0;" ::: "memory")

__device__ __forceinline__ void ldsm4(uint32_t* r, uint32_t addr) {
    asm volatile("ldmatrix.sync.aligned.m8n8.x4.shared.b16 {%0,%1,%2,%3}, [%4];"
                 : "=r"(r[0]), "=r"(r[1]), "=r"(r[2]), "=r"(r[3]) : "r"(addr));
}
__device__ __forceinline__ void ldsm4t(uint32_t* r, uint32_t addr) {
    asm volatile("ldmatrix.sync.aligned.m8n8.x4.trans.shared.b16 {%0,%1,%2,%3}, [%4];"
                 : "=r"(r[0]), "=r"(r[1]), "=r"(r[2]), "=r"(r[3]) : "r"(addr));
}
__device__ __forceinline__ void mma16816(float* d, const uint32_t* a, uint32_t b0, uint32_t b1) {
    asm volatile("mma.sync.aligned.m16n8k16.row.col.f32.f16.f16.f32 "
                 "{%0,%1,%2,%3}, {%4,%5,%6,%7}, {%8,%9}, {%0,%1,%2,%3};"
                 : "+f"(d[0]), "+f"(d[1]), "+f"(d[2]), "+f"(d[3])
                 : "r"(a[0]), "r"(a[1]), "r"(a[2]), "r"(a[3]), "r"(b0), "r"(b1));
}

// ---------------- SMEM layout ----------------
// A: 128 rows x 32 fp16 (64B) + 16B pad = 80B stride  -> 10240 B
// B: 32 k-rows x 128 fp16 (256B) + 16B pad = 272B stride -> 8704 B
#define AST 80
#define BST 272
#define OFF_TOK  0
#define OFF_HR   512
#define OFF_GWS  1024
#define OFF_TILE 1536
#define A_OFF 0
#define B_OFF 10240
#define BUF_SZ 18944
#define SMEM_SZ (OFF_TILE + 2 * BUF_SZ)   // 39424

// ---------------- kernel 0: zero counters ----------------
__global__ void k_zero() { if (threadIdx.x < NE) g_cnt[threadIdx.x] = 0; }

// ---------------- gating: one warp per token ----------------
__global__ void k_gate(const float* __restrict__ x,
                       const float* __restrict__ gw,
                       const float* __restrict__ gb) {
    int warp = (blockIdx.x * blockDim.x + threadIdx.x) >> 5;
    int lane = threadIdx.x & 31;
    if (warp >= NT) return;
    const float* xr = x + (size_t)warp * DD;
    float acc[NE];
#pragma unroll
    for (int e = 0; e < NE; e++) acc[e] = 0.0f;
    for (int d = lane; d < DD; d += 32) {
        float xv = xr[d];
#pragma unroll
        for (int e = 0; e < NE; e++) acc[e] += xv * gw[d * NE + e];
    }
#pragma unroll
    for (int e = 0; e < NE; e++) {
#pragma unroll
        for (int o = 16; o > 0; o >>= 1)
            acc[e] += __shfl_xor_sync(0xffffffffu, acc[e], o);
    }
    if (lane == 0) {
        float z[NE]; float m = -1e30f;
#pragma unroll
        for (int e = 0; e < NE; e++) { z[e] = acc[e] + gb[e]; m = fmaxf(m, z[e]); }
        float s = 0.0f;
#pragma unroll
        for (int e = 0; e < NE; e++) { z[e] = expf(z[e] - m); s += z[e]; }
        int i1 = 0;
#pragma unroll
        for (int e = 1; e < NE; e++) if (z[e] > z[i1]) i1 = e;
        int i2 = (i1 == 0) ? 1 : 0;
#pragma unroll
        for (int e = 0; e < NE; e++) if (e != i1 && z[e] > z[i2]) i2 = e;
        float inv = 1.0f / s;
        int es[2] = { i1, i2 };
#pragma unroll
        for (int k = 0; k < TOPK; k++) {
            int e = es[k];
            int slot = atomicAdd(&g_cnt[e], 1);
            g_tok [e * NT + slot] = warp;
            g_gw  [e * NT + slot] = z[e] * inv;
            g_hrow[e * NT + slot] = warp * TOPK + k;
        }
    }
}

// ---------------- fp32 -> fp16 preconvert ----------------
__global__ void k_conv(const float* __restrict__ src, __half* __restrict__ dst, int n4) {
    int i = blockIdx.x * blockDim.x + threadIdx.x;
    if (i >= n4) return;
    float4 v = ((const float4*)src)[i];
    __half2 a = __floats2half2_rn(v.x, v.y);
    __half2 b = __floats2half2_rn(v.z, v.w);
    ((uint2*)dst)[i] = make_uint2(*(uint32_t*)&a, *(uint32_t*)&b);
}

// ---------------- tile fill (cp.async) ----------------
__device__ __forceinline__ void fill_tiles(uint32_t tb, int tid,
                                           const __half* __restrict__ A, int a_ld,
                                           const int* rows,
                                           const __half* __restrict__ B, int b_ld,
                                           int n0, int k0) {
    // A: 128 rows x 32 fp16 = 4 x 16B chunks/row -> 512 chunks
#pragma unroll
    for (int i = 0; i < 2; i++) {
        int id = tid + i * 256;
        int r = id >> 2, c = id & 3;
        int t = rows[r];
        size_t off = (size_t)(t < 0 ? 0 : t) * a_ld + k0 + c * 8;
        cp16(tb + A_OFF + r * AST + c * 16, A + off, (t < 0) ? 0u : 16u);
    }
    // B: 32 k-rows x 128 fp16 = 16 x 16B chunks/row -> 512 chunks
#pragma unroll
    for (int i = 0; i < 2; i++) {
        int id = tid + i * 256;
        int r = id >> 4, c = id & 15;
        size_t off = (size_t)(k0 + r) * b_ld + n0 + c * 8;
        cp16(tb + B_OFF + r * BST + c * 16, B + off, 16u);
    }
}

// ---------------- mma mainloop for one 32-K chunk ----------------
// warp tile: 64 (m) x 32 (n); acc[4 m-tiles][4 n8-tiles][4]
__device__ __forceinline__ void compute_chunk(uint32_t tb, int lane, int wm, int wn,
                                              float acc[4][4][4]) {
    int t  = lane >> 3;
    int lr = lane & 7;
#pragma unroll
    for (int k16 = 0; k16 < KC; k16 += 16) {
        uint32_t a[4][4];
#pragma unroll
        for (int mt = 0; mt < 4; mt++) {
            uint32_t addr = tb + A_OFF + (uint32_t)(wm + mt * 16 + (t & 1) * 8 + lr) * AST
                          + (uint32_t)(k16 + (t >> 1) * 8) * 2;
            ldsm4(a[mt], addr);
        }
#pragma unroll
        for (int j = 0; j < 2; j++) {
            uint32_t b[4];
            uint32_t addr = tb + B_OFF + (uint32_t)(k16 + (t & 1) * 8 + lr) * BST
                          + (uint32_t)(wn + j * 16 + (t >> 1) * 8) * 2;
            ldsm4t(b, addr);
#pragma unroll
            for (int mt = 0; mt < 4; mt++) {
                mma16816(acc[mt][j * 2 + 0], a[mt], b[0], b[1]);
                mma16816(acc[mt][j * 2 + 1], a[mt], b[2], b[3]);
            }
        }
    }
}

// ---------------- FC1: h[hrow] = relu(x[tok] @ w1[e] + b1[e]) -> fp16 ----------------
__global__ void __launch_bounds__(256, 2)
k_fc1(const float* __restrict__ b1) {
    int e = blockIdx.z;
    int cnt = g_cnt[e];
    int m0 = blockIdx.y * BM;
    if (m0 >= cnt) return;
    int n0 = blockIdx.x * BN;

    extern __shared__ char smem[];
    uint32_t sb = smem_u32(smem);
    int tid = threadIdx.x, wid = tid >> 5, lane = tid & 31;
    int* toks  = (int*)(smem + OFF_TOK);
    int* hrows = (int*)(smem + OFF_HR);
    if (tid < BM) {
        int s = m0 + tid;
        toks [tid] = (s < cnt) ? g_tok [e * NT + s] : -1;
        hrows[tid] = (s < cnt) ? g_hrow[e * NT + s] : -1;
    }
    __syncthreads();

    const __half* W = g_w1f + (size_t)e * DD * HH;

    float acc[4][4][4];
#pragma unroll
    for (int a = 0; a < 4; a++)
#pragma unroll
        for (int b = 0; b < 4; b++)
#pragma unroll
            for (int c = 0; c < 4; c++) acc[a][b][c] = 0.0f;

    int wm = (wid >> 2) * 64, wn = (wid & 3) * 32;
    const int NCH = DD / KC;   // 32

    fill_tiles(sb + OFF_TILE, tid, g_xf, DD, toks, W, HH, n0, 0);
    CP_COMMIT();
    int buf = 0;
    for (int c = 0; c < NCH; c++) {
        if (c + 1 < NCH) {
            fill_tiles(sb + OFF_TILE + (buf ^ 1) * BUF_SZ, tid, g_xf, DD, toks,
                       W, HH, n0, (c + 1) * KC);
            CP_COMMIT();
            CP_WAIT1();
        } else {
            CP_WAIT0();
        }
        __syncthreads();
        compute_chunk(sb + OFF_TILE + buf * BUF_SZ, lane, wm, wn, acc);
        __syncthreads();
        buf ^= 1;
    }

    // epilogue: bias + relu -> fp16 h
    const float* bb = b1 + (size_t)e * HH + n0;
#pragma unroll
    for (int mt = 0; mt < 4; mt++) {
#pragma unroll
        for (int nt = 0; nt < 4; nt++) {
            int col = wn + nt * 8 + (lane & 3) * 2;
            float bv0 = bb[col], bv1 = bb[col + 1];
#pragma unroll
            for (int half = 0; half < 2; half++) {
                int li = wm + mt * 16 + (lane >> 2) + half * 8;
                int hr = hrows[li];
                if (hr < 0) continue;
                float h0 = fmaxf(acc[mt][nt][half * 2 + 0] + bv0, 0.0f);
                float h1 = fmaxf(acc[mt][nt][half * 2 + 1] + bv1, 0.0f);
                __half2 hp = __floats2half2_rn(h0, h1);
                *(uint32_t*)(g_hf + (size_t)hr * HH + n0 + col) = *(uint32_t*)&hp;
            }
        }
    }
}

// ---------------- FC2: y[hrow] = gate * (h[hrow] @ w2[e] + b2[e]) ----------------
__global__ void __launch_bounds__(256, 2)
k_fc2(const float* __restrict__ b2) {
    int e = blockIdx.z;
    int cnt = g_cnt[e];
    int m0 = blockIdx.y * BM;
    if (m0 >= cnt) return;
    int n0 = blockIdx.x * BN;

    extern __shared__ char smem[];
    uint32_t sb = smem_u32(smem);
    int tid = threadIdx.x, wid = tid >> 5, lane = tid & 31;
    int*   hrows = (int*)(smem + OFF_HR);
    float* gws   = (float*)(smem + OFF_GWS);
    if (tid < BM) {
        int s = m0 + tid;
        hrows[tid] = (s < cnt) ? g_hrow[e * NT + s] : -1;
        gws  [tid] = (s < cnt) ? g_gw  [e * NT + s] : 0.0f;
    }
    __syncthreads();

    const __half* W = g_w2f + (size_t)e * HH * DD;

    float acc[4][4][4];
#pragma unroll
    for (int a = 0; a < 4; a++)
#pragma unroll
        for (int b = 0; b < 4; b++)
#pragma unroll
            for (int c = 0; c < 4; c++) acc[a][b][c] = 0.0f;

    int wm = (wid >> 2) * 64, wn = (wid & 3) * 32;
    const int NCH = HH / KC;   // 128

    fill_tiles(sb + OFF_TILE, tid, g_hf, HH, hrows, W, DD, n0, 0);
    CP_COMMIT();
    int buf = 0;
    for (int c = 0; c < NCH; c++) {
        if (c + 1 < NCH) {
            fill_tiles(sb + OFF_TILE + (buf ^ 1) * BUF_SZ, tid, g_hf, HH, hrows,
                       W, DD, n0, (c + 1) * KC);
            CP_COMMIT();
            CP_WAIT1();
        } else {
            CP_WAIT0();
        }
        __syncthreads();
        compute_chunk(sb + OFF_TILE + buf * BUF_SZ, lane, wm, wn, acc);
        __syncthreads();
        buf ^= 1;
    }

    const float* bb = b2 + (size_t)e * DD + n0;
#pragma unroll
    for (int mt = 0; mt < 4; mt++) {
#pragma unroll
        for (int nt = 0; nt < 4; nt++) {
            int col = wn + nt * 8 + (lane & 3) * 2;
            float bv0 = bb[col], bv1 = bb[col + 1];
#pragma unroll
            for (int half = 0; half < 2; half++) {
                int li = wm + mt * 16 + (lane >> 2) + half * 8;
                int hr = hrows[li];
                if (hr < 0) continue;
                float g = gws[li];
                float2 o;
                o.x = g * (acc[mt][nt][half * 2 + 0] + bv0);
                o.y = g * (acc[mt][nt][half * 2 + 1] + bv1);
                *(float2*)(g_y + (size_t)hr * DD + n0 + col) = o;
            }
        }
    }
}

// ---------------- combine: out[t] = y[2t] + y[2t+1] ----------------
__global__ void k_combine(float* __restrict__ out) {
    int i = blockIdx.x * blockDim.x + threadIdx.x;
    if (i >= NT * DD / 4) return;
    int t  = i >> 8;
    int d4 = i & 255;
    const float4* y4 = (const float4*)g_y;
    float4 a = y4[(size_t)(2 * t) * 256 + d4];
    float4 b = y4[(size_t)(2 * t + 1) * 256 + d4];
    float4 o; o.x = a.x + b.x; o.y = a.y + b.y; o.z = a.z + b.z; o.w = a.w + b.w;
    ((float4*)out)[i] = o;
}

// ---------------- launch ----------------
extern "C" void kernel_launch(void* const* d_in, const int* in_sizes, int n_in,
                              void* d_out, int out_size) {
    const float* x  = (const float*)d_in[0];
    const float* gw = (const float*)d_in[1];
    const float* gb = (const float*)d_in[2];
    const float* w1 = (const float*)d_in[3];
    const float* b1 = (const float*)d_in[4];
    const float* w2 = (const float*)d_in[5];
    const float* b2 = (const float*)d_in[6];
    float* out = (float*)d_out;

    cudaFuncSetAttribute(k_fc1, cudaFuncAttributeMaxDynamicSharedMemorySize, SMEM_SZ);
    cudaFuncSetAttribute(k_fc2, cudaFuncAttributeMaxDynamicSharedMemorySize, SMEM_SZ);

    k_zero<<<1, 32>>>();
    k_gate<<<NT / 4, 128>>>(x, gw, gb);

    __half *xf, *w1f, *w2f;
    cudaGetSymbolAddress((void**)&xf,  g_xf);
    cudaGetSymbolAddress((void**)&w1f, g_w1f);
    cudaGetSymbolAddress((void**)&w2f, g_w2f);

    int nx = NT * DD / 4;
    int nw = NE * DD * HH / 4;
    k_conv<<<(nx + 255) / 256, 256>>>(x,  xf,  nx);
    k_conv<<<(nw + 255) / 256, 256>>>(w1, w1f, nw);
    k_conv<<<(nw + 255) / 256, 256>>>(w2, w2f, nw);

    dim3 g1(HH / BN, NT / BM, NE);   // 32 x 32 x 8
    k_fc1<<<g1, 256, SMEM_SZ>>>(b1);

    dim3 g2(DD / BN, NT / BM, NE);   // 8 x 32 x 8
    k_fc2<<<g2, 256, SMEM_SZ>>>(b2);

    k_combine<<<(NT * DD / 4 + 255) / 256, 256>>>(out);
}

// round 10
// speedup vs baseline: 7.7034x; 1.0138x over previous
#include <cuda_runtime.h>
#include <cuda_fp16.h>
#include <math.h>
#include <stdint.h>

// Problem constants
#define NT   4096   // B*T tokens
#define DD   1024   // model dim
#define HH   4096   // hidden dim
#define NE   8      // experts
#define TOPK 2

#define BM 128
#define BN 128
#define KC 32
#define STAGES 4

// ---------------- scratch (static device, no allocation) ----------------
__device__ int   g_cnt[NE];
__device__ int   g_tok [NE * NT];
__device__ float g_gw  [NE * NT];
__device__ int   g_hrow[NE * NT];

__device__ __half g_xf[(size_t)NT * DD];
__device__ __half g_w1f[(size_t)NE * DD * HH];
__device__ __half g_w2f[(size_t)NE * HH * DD];
__device__ __half g_hf[(size_t)NT * TOPK * HH];
__device__ float  g_y[(size_t)NT * TOPK * DD];

// ---------------- PTX helpers (plain sm_103-safe) ----------------
__device__ __forceinline__ uint32_t smem_u32(const void* p) {
    uint32_t a;
    asm("{ .reg .u64 t; cvta.to.shared.u64 t, %1; cvt.u32.u64 %0, t; }" : "=r"(a) : "l"(p));
    return a;
}
__device__ __forceinline__ void cp16(uint32_t dst, const void* src, uint32_t srcsize) {
    asm volatile("cp.async.cg.shared.global [%0], [%1], 16, %2;"
                 :: "r"(dst), "l"(src), "r"(srcsize) : "memory");
}
#define CP_COMMIT()  asm volatile("cp.async.commit_group;" ::: "memory")
#define CP_WAIT2()   asm volatile("cp.async.wait_group 2;" ::: "memory")
#define CP_WAIT1()   asm volatile("cp.async.wait_group 1;" ::: "memory")
#define CP_WAIT0()   asm volatile("cp.async.wait_group 0;" ::: "memory")

__device__ __forceinline__ void ldsm4(uint32_t* r, uint32_t addr) {
    asm volatile("ldmatrix.sync.aligned.m8n8.x4.shared.b16 {%0,%1,%2,%3}, [%4];"
                 : "=r"(r[0]), "=r"(r[1]), "=r"(r[2]), "=r"(r[3]) : "r"(addr));
}
__device__ __forceinline__ void ldsm4t(uint32_t* r, uint32_t addr) {
    asm volatile("ldmatrix.sync.aligned.m8n8.x4.trans.shared.b16 {%0,%1,%2,%3}, [%4];"
                 : "=r"(r[0]), "=r"(r[1]), "=r"(r[2]), "=r"(r[3]) : "r"(addr));
}
__device__ __forceinline__ void mma16816(float* d, const uint32_t* a, uint32_t b0, uint32_t b1) {
    asm volatile("mma.sync.aligned.m16n8k16.row.col.f32.f16.f16.f32 "
                 "{%0,%1,%2,%3}, {%4,%5,%6,%7}, {%8,%9}, {%0,%1,%2,%3};"
                 : "+f"(d[0]), "+f"(d[1]), "+f"(d[2]), "+f"(d[3])
                 : "r"(a[0]), "r"(a[1]), "r"(a[2]), "r"(a[3]), "r"(b0), "r"(b1));
}

// ---------------- SMEM layout ----------------
// A: 128 rows x 32 fp16 (64B) + 16B pad = 80B stride  -> 10240 B
// B: 32 k-rows x 128 fp16 (256B) + 16B pad = 272B stride -> 8704 B
#define AST 80
#define BST 272
#define OFF_TOK  0
#define OFF_HR   512
#define OFF_GWS  1024
#define OFF_TILE 1536
#define A_OFF 0
#define B_OFF 10240
#define BUF_SZ 18944
#define SMEM_SZ (OFF_TILE + STAGES * BUF_SZ)   // 77312

// ---------------- kernel 0: zero counters ----------------
__global__ void k_zero() { if (threadIdx.x < NE) g_cnt[threadIdx.x] = 0; }

// ---------------- gating: one warp per token ----------------
__global__ void k_gate(const float* __restrict__ x,
                       const float* __restrict__ gw,
                       const float* __restrict__ gb) {
    int warp = (blockIdx.x * blockDim.x + threadIdx.x) >> 5;
    int lane = threadIdx.x & 31;
    if (warp >= NT) return;
    const float* xr = x + (size_t)warp * DD;
    float acc[NE];
#pragma unroll
    for (int e = 0; e < NE; e++) acc[e] = 0.0f;
    for (int d = lane; d < DD; d += 32) {
        float xv = xr[d];
#pragma unroll
        for (int e = 0; e < NE; e++) acc[e] += xv * gw[d * NE + e];
    }
#pragma unroll
    for (int e = 0; e < NE; e++) {
#pragma unroll
        for (int o = 16; o > 0; o >>= 1)
            acc[e] += __shfl_xor_sync(0xffffffffu, acc[e], o);
    }
    if (lane == 0) {
        float z[NE]; float m = -1e30f;
#pragma unroll
        for (int e = 0; e < NE; e++) { z[e] = acc[e] + gb[e]; m = fmaxf(m, z[e]); }
        float s = 0.0f;
#pragma unroll
        for (int e = 0; e < NE; e++) { z[e] = expf(z[e] - m); s += z[e]; }
        int i1 = 0;
#pragma unroll
        for (int e = 1; e < NE; e++) if (z[e] > z[i1]) i1 = e;
        int i2 = (i1 == 0) ? 1 : 0;
#pragma unroll
        for (int e = 0; e < NE; e++) if (e != i1 && z[e] > z[i2]) i2 = e;
        float inv = 1.0f / s;
        int es[2] = { i1, i2 };
#pragma unroll
        for (int k = 0; k < TOPK; k++) {
            int e = es[k];
            int slot = atomicAdd(&g_cnt[e], 1);
            g_tok [e * NT + slot] = warp;
            g_gw  [e * NT + slot] = z[e] * inv;
            g_hrow[e * NT + slot] = warp * TOPK + k;
        }
    }
}

// ---------------- fp32 -> fp16 preconvert ----------------
__global__ void k_conv(const float* __restrict__ src, __half* __restrict__ dst, int n4) {
    int i = blockIdx.x * blockDim.x + threadIdx.x;
    if (i >= n4) return;
    float4 v = ((const float4*)src)[i];
    __half2 a = __floats2half2_rn(v.x, v.y);
    __half2 b = __floats2half2_rn(v.z, v.w);
    ((uint2*)dst)[i] = make_uint2(*(uint32_t*)&a, *(uint32_t*)&b);
}

// ---------------- tile fill (cp.async) ----------------
__device__ __forceinline__ void fill_tiles(uint32_t tb, int tid,
                                           const __half* __restrict__ A, int a_ld,
                                           const int* rows,
                                           const __half* __restrict__ B, int b_ld,
                                           int n0, int k0) {
    // A: 128 rows x 32 fp16 = 4 x 16B chunks/row -> 512 chunks
#pragma unroll
    for (int i = 0; i < 2; i++) {
        int id = tid + i * 256;
        int r = id >> 2, c = id & 3;
        int t = rows[r];
        size_t off = (size_t)(t < 0 ? 0 : t) * a_ld + k0 + c * 8;
        cp16(tb + A_OFF + r * AST + c * 16, A + off, (t < 0) ? 0u : 16u);
    }
    // B: 32 k-rows x 128 fp16 = 16 x 16B chunks/row -> 512 chunks
#pragma unroll
    for (int i = 0; i < 2; i++) {
        int id = tid + i * 256;
        int r = id >> 4, c = id & 15;
        size_t off = (size_t)(k0 + r) * b_ld + n0 + c * 8;
        cp16(tb + B_OFF + r * BST + c * 16, B + off, 16u);
    }
}

// ---------------- mma mainloop for one 32-K chunk ----------------
// warp tile: 64 (m) x 32 (n); acc[4 m-tiles][4 n8-tiles][4]
__device__ __forceinline__ void compute_chunk(uint32_t tb, int lane, int wm, int wn,
                                              float acc[4][4][4]) {
    int t  = lane >> 3;
    int lr = lane & 7;
#pragma unroll
    for (int k16 = 0; k16 < KC; k16 += 16) {
        uint32_t a[4][4];
#pragma unroll
        for (int mt = 0; mt < 4; mt++) {
            uint32_t addr = tb + A_OFF + (uint32_t)(wm + mt * 16 + (t & 1) * 8 + lr) * AST
                          + (uint32_t)(k16 + (t >> 1) * 8) * 2;
            ldsm4(a[mt], addr);
        }
#pragma unroll
        for (int j = 0; j < 2; j++) {
            uint32_t b[4];
            uint32_t addr = tb + B_OFF + (uint32_t)(k16 + (t & 1) * 8 + lr) * BST
                          + (uint32_t)(wn + j * 16 + (t >> 1) * 8) * 2;
            ldsm4t(b, addr);
#pragma unroll
            for (int mt = 0; mt < 4; mt++) {
                mma16816(acc[mt][j * 2 + 0], a[mt], b[0], b[1]);
                mma16816(acc[mt][j * 2 + 1], a[mt], b[2], b[3]);
            }
        }
    }
}

// pipelined mainloop shared by both FC kernels
// NCH must be > STAGES-1
__device__ __forceinline__ void gemm_mainloop(uint32_t sb, int tid, int lane, int wm, int wn,
                                              const __half* __restrict__ A, int a_ld,
                                              const int* rows,
                                              const __half* __restrict__ B, int b_ld,
                                              int n0, int NCH, float acc[4][4][4]) {
    // prologue: fill stages 0..STAGES-2
#pragma unroll
    for (int s = 0; s < STAGES - 1; s++) {
        fill_tiles(sb + OFF_TILE + s * BUF_SZ, tid, A, a_ld, rows, B, b_ld, n0, s * KC);
        CP_COMMIT();
    }
    int stage = 0;
    for (int c = 0; c < NCH; c++) {
        // wait for stage c's fill (pending groups: min(STAGES-1, NCH-c))
        if (c + 2 < NCH)      CP_WAIT2();
        else if (c + 1 < NCH) CP_WAIT1();
        else                  CP_WAIT0();
        __syncthreads();   // fills visible to all warps; all warps done computing chunk c-1
        if (c + STAGES - 1 < NCH) {
            int fs = stage + STAGES - 1; if (fs >= STAGES) fs -= STAGES;
            fill_tiles(sb + OFF_TILE + fs * BUF_SZ, tid, A, a_ld, rows, B, b_ld, n0,
                       (c + STAGES - 1) * KC);
            CP_COMMIT();
        }
        compute_chunk(sb + OFF_TILE + stage * BUF_SZ, lane, wm, wn, acc);
        stage++; if (stage >= STAGES) stage = 0;
    }
}

// ---------------- FC1: h[hrow] = relu(x[tok] @ w1[e] + b1[e]) -> fp16 ----------------
__global__ void __launch_bounds__(256, 2)
k_fc1(const float* __restrict__ b1) {
    int e = blockIdx.z;
    int cnt = g_cnt[e];
    int m0 = blockIdx.y * BM;
    if (m0 >= cnt) return;
    int n0 = blockIdx.x * BN;

    extern __shared__ char smem[];
    uint32_t sb = smem_u32(smem);
    int tid = threadIdx.x, wid = tid >> 5, lane = tid & 31;
    int* toks  = (int*)(smem + OFF_TOK);
    int* hrows = (int*)(smem + OFF_HR);
    if (tid < BM) {
        int s = m0 + tid;
        toks [tid] = (s < cnt) ? g_tok [e * NT + s] : -1;
        hrows[tid] = (s < cnt) ? g_hrow[e * NT + s] : -1;
    }
    __syncthreads();

    const __half* W = g_w1f + (size_t)e * DD * HH;

    float acc[4][4][4];
#pragma unroll
    for (int a = 0; a < 4; a++)
#pragma unroll
        for (int b = 0; b < 4; b++)
#pragma unroll
            for (int c = 0; c < 4; c++) acc[a][b][c] = 0.0f;

    int wm = (wid >> 2) * 64, wn = (wid & 3) * 32;

    gemm_mainloop(sb, tid, lane, wm, wn, g_xf, DD, toks, W, HH, n0, DD / KC, acc);

    // epilogue: bias + relu -> fp16 h
    const float* bb = b1 + (size_t)e * HH + n0;
#pragma unroll
    for (int mt = 0; mt < 4; mt++) {
#pragma unroll
        for (int nt = 0; nt < 4; nt++) {
            int col = wn + nt * 8 + (lane & 3) * 2;
            float bv0 = bb[col], bv1 = bb[col + 1];
#pragma unroll
            for (int half = 0; half < 2; half++) {
                int li = wm + mt * 16 + (lane >> 2) + half * 8;
                int hr = hrows[li];
                if (hr < 0) continue;
                float h0 = fmaxf(acc[mt][nt][half * 2 + 0] + bv0, 0.0f);
                float h1 = fmaxf(acc[mt][nt][half * 2 + 1] + bv1, 0.0f);
                __half2 hp = __floats2half2_rn(h0, h1);
                *(uint32_t*)(g_hf + (size_t)hr * HH + n0 + col) = *(uint32_t*)&hp;
            }
        }
    }
}

// ---------------- FC2: y[hrow] = gate * (h[hrow] @ w2[e] + b2[e]) ----------------
__global__ void __launch_bounds__(256, 2)
k_fc2(const float* __restrict__ b2) {
    int e = blockIdx.z;
    int cnt = g_cnt[e];
    int m0 = blockIdx.y * BM;
    if (m0 >= cnt) return;
    int n0 = blockIdx.x * BN;

    extern __shared__ char smem[];
    uint32_t sb = smem_u32(smem);
    int tid = threadIdx.x, wid = tid >> 5, lane = tid & 31;
    int*   hrows = (int*)(smem + OFF_HR);
    float* gws   = (float*)(smem + OFF_GWS);
    if (tid < BM) {
        int s = m0 + tid;
        hrows[tid] = (s < cnt) ? g_hrow[e * NT + s] : -1;
        gws  [tid] = (s < cnt) ? g_gw  [e * NT + s] : 0.0f;
    }
    __syncthreads();

    const __half* W = g_w2f + (size_t)e * HH * DD;

    float acc[4][4][4];
#pragma unroll
    for (int a = 0; a < 4; a++)
#pragma unroll
        for (int b = 0; b < 4; b++)
#pragma unroll
            for (int c = 0; c < 4; c++) acc[a][b][c] = 0.0f;

    int wm = (wid >> 2) * 64, wn = (wid & 3) * 32;

    gemm_mainloop(sb, tid, lane, wm, wn, g_hf, HH, hrows, W, DD, n0, HH / KC, acc);

    const float* bb = b2 + (size_t)e * DD + n0;
#pragma unroll
    for (int mt = 0; mt < 4; mt++) {
#pragma unroll
        for (int nt = 0; nt < 4; nt++) {
            int col = wn + nt * 8 + (lane & 3) * 2;
            float bv0 = bb[col], bv1 = bb[col + 1];
#pragma unroll
            for (int half = 0; half < 2; half++) {
                int li = wm + mt * 16 + (lane >> 2) + half * 8;
                int hr = hrows[li];
                if (hr < 0) continue;
                float g = gws[li];
                float2 o;
                o.x = g * (acc[mt][nt][half * 2 + 0] + bv0);
                o.y = g * (acc[mt][nt][half * 2 + 1] + bv1);
                *(float2*)(g_y + (size_t)hr * DD + n0 + col) = o;
            }
        }
    }
}

// ---------------- combine: out[t] = y[2t] + y[2t+1] ----------------
__global__ void k_combine(float* __restrict__ out) {
    int i = blockIdx.x * blockDim.x + threadIdx.x;
    if (i >= NT * DD / 4) return;
    int t  = i >> 8;
    int d4 = i & 255;
    const float4* y4 = (const float4*)g_y;
    float4 a = y4[(size_t)(2 * t) * 256 + d4];
    float4 b = y4[(size_t)(2 * t + 1) * 256 + d4];
    float4 o; o.x = a.x + b.x; o.y = a.y + b.y; o.z = a.z + b.z; o.w = a.w + b.w;
    ((float4*)out)[i] = o;
}

// ---------------- launch ----------------
extern "C" void kernel_launch(void* const* d_in, const int* in_sizes, int n_in,
                              void* d_out, int out_size) {
    const float* x  = (const float*)d_in[0];
    const float* gw = (const float*)d_in[1];
    const float* gb = (const float*)d_in[2];
    const float* w1 = (const float*)d_in[3];
    const float* b1 = (const float*)d_in[4];
    const float* w2 = (const float*)d_in[5];
    const float* b2 = (const float*)d_in[6];
    float* out = (float*)d_out;

    cudaFuncSetAttribute(k_fc1, cudaFuncAttributeMaxDynamicSharedMemorySize, SMEM_SZ);
    cudaFuncSetAttribute(k_fc2, cudaFuncAttributeMaxDynamicSharedMemorySize, SMEM_SZ);

    k_zero<<<1, 32>>>();
    k_gate<<<NT / 4, 128>>>(x, gw, gb);

    __half *xf, *w1f, *w2f;
    cudaGetSymbolAddress((void**)&xf,  g_xf);
    cudaGetSymbolAddress((void**)&w1f, g_w1f);
    cudaGetSymbolAddress((void**)&w2f, g_w2f);

    int nx = NT * DD / 4;
    int nw = NE * DD * HH / 4;
    k_conv<<<(nx + 255) / 256, 256>>>(x,  xf,  nx);
    k_conv<<<(nw + 255) / 256, 256>>>(w1, w1f, nw);
    k_conv<<<(nw + 255) / 256, 256>>>(w2, w2f, nw);

    dim3 g1(HH / BN, NT / BM, NE);   // 32 x 32 x 8
    k_fc1<<<g1, 256, SMEM_SZ>>>(b1);

    dim3 g2(DD / BN, NT / BM, NE);   // 8 x 32 x 8
    k_fc2<<<g2, 256, SMEM_SZ>>>(b2);

    k_combine<<<(NT * DD / 4 + 255) / 256, 256>>>(out);
}